// round 8
// baseline (speedup 1.0000x reference)
#include <cuda_runtime.h>
#include <math.h>
#include <stdint.h>

#define TT 512
#define BB 64
#define HH 512
#define GRID 128
#define NTHREADS 512
#define AST 516                      // padded row stride (floats) everywhere
#define APF (BB * AST)               // 33,024 floats per padded [64x512] tile
#define HALF_B (32 * AST * 4)        // 66,048 bytes per 32-row half

// ---- smem layout (bytes) ----
#define OFF_CH_F   33024             // float index of ch
#define OFF_SL_F   34048             // float index of sl
#define OFF_MBAR_B 145408            // byte offset of mbarriers
#define SMEM_TOTAL 145424

// ---------------- device globals (no allocation allowed) ----------------
__device__ unsigned long long g_arrive;
__device__ unsigned long long g_release;
__device__ float g_xpad[TT * APF];           // padded x           (67.6 MB)
__device__ float g_hpad[APF];                // padded h_prev
__device__ float g_spad[5][APF];             // padded states s0..s4
__device__ float g_wt0[1024 * 1024];         // W0^T  [col][k]     (4 MB)
__device__ float g_wts[8][1024 * 512];       // Ws^T  [i][col][k]  (16 MB)

__device__ __forceinline__ void fma2(unsigned long long &d, unsigned long long a,
                                     unsigned long long b) {
    asm("fma.rn.f32x2 %0, %1, %2, %0;" : "+l"(d) : "l"(a), "l"(b));
}

// Monotonic grid barrier: safe across graph replays (counters never reset).
// 128 CTAs co-resident (1 CTA/SM via 145KB smem), so spinning is safe.
__device__ __forceinline__ void grid_bar(int tid) {
    __syncthreads();
    if (tid == 0) {
        __threadfence();
        unsigned long long a = atomicAdd(&g_arrive, 1ULL) + 1ULL;
        unsigned long long phase = (a + (GRID - 1)) / GRID;
        if (a == phase * (unsigned long long)GRID) {
            asm volatile("st.release.gpu.u64 [%0], %1;"
                         :: "l"(&g_release), "l"(phase) : "memory");
        } else {
            unsigned long long v;
            do {
                asm volatile("ld.acquire.gpu.u64 %0, [%1];"
                             : "=l"(v) : "l"(&g_release) : "memory");
            } while (v < phase);
        }
        __threadfence();
    }
    __syncthreads();
}

// One-thread TMA bulk stage: expect_tx + 1D bulk copy global->smem.
__device__ __forceinline__ void bulk_stage(unsigned int dst, const float* src,
                                           unsigned int bytes, unsigned int mbar) {
    asm volatile("mbarrier.arrive.expect_tx.shared.b64 _, [%0], %1;"
                 :: "r"(mbar), "r"(bytes) : "memory");
    asm volatile(
        "cp.async.bulk.shared::cluster.global.mbarrier::complete_tx::bytes "
        "[%0], [%1], %2, [%3];"
        :: "r"(dst), "l"(src), "r"(bytes), "r"(mbar) : "memory");
}

__device__ __forceinline__ void mbar_wait(unsigned int mbar, unsigned int phase) {
    asm volatile(
        "{\n\t"
        ".reg .pred P;\n\t"
        "WL_%=:\n\t"
        "mbarrier.try_wait.parity.acquire.cta.shared::cta.b64 P, [%0], %1, 0x989680;\n\t"
        "@P bra WD_%=;\n\t"
        "bra WL_%=;\n\t"
        "WD_%=:\n\t"
        "}"
        :: "r"(mbar), "r"(phase) : "memory");
}

// GEMM over rows [16*I0, 16*I0+32) for this thread's fragment; full warp k-slice.
template <int NSETS, int I0>
__device__ __forceinline__ void gemm_rows(const float* __restrict__ as,
        const float* __restrict__ wcolp, long long wstride,
        int wk, int ri, unsigned long long (&acc)[4][4]) {
    constexpr int KW = (NSETS == 2) ? 64 : 32;   // k's per warp (full phase)
    constexpr int T4 = KW / 4;
    const int kl0 = wk * KW;

    ulonglong2 wcur[4], wnxt[4];
#pragma unroll
    for (int j = 0; j < 4; ++j)
        wcur[j] = __ldg(reinterpret_cast<const ulonglong2*>(
            wcolp + j * wstride + kl0));
#pragma unroll
    for (int t4 = 0; t4 < T4; ++t4) {
        const int kl = kl0 + t4 * 4;
        ulonglong2 a2[2];
#pragma unroll
        for (int ii = 0; ii < 2; ++ii)
            a2[ii] = *reinterpret_cast<const ulonglong2*>(
                as + (ri + 16 * (I0 + ii)) * AST + kl);
        if (t4 + 1 < T4) {
#pragma unroll
            for (int j = 0; j < 4; ++j)
                wnxt[j] = __ldg(reinterpret_cast<const ulonglong2*>(
                    wcolp + j * wstride + kl + 4));
        }
#pragma unroll
        for (int j = 0; j < 4; ++j)
#pragma unroll
            for (int ii = 0; ii < 2; ++ii) {
                fma2(acc[I0 + ii][j], a2[ii].x, wcur[j].x);
                fma2(acc[I0 + ii][j], a2[ii].y, wcur[j].y);
            }
#pragma unroll
        for (int j = 0; j < 4; ++j) wcur[j] = wnxt[j];
    }
}

// One DAG level. NPH accumulate phases of K=512 (L0: x then h).
// NSETS==2: warps 0-7 set0, warps 8-15 set1. Sources are padded (stride AST).
template <int NSETS, int NPH>
__device__ __forceinline__ void do_level(float* smem, unsigned int su, int tid,
        const float* srcA0, const float* srcA1,
        const float* wt0, const float* wt1, long long wstride, int colbase,
        int act0, int act1, int pred0, int pred1, int st0, int st1,
        float* gd0, float* gd1, const float* __restrict__ hprev, int &par) {
    float* as = smem;
    float* ch = smem + OFF_CH_F;
    float* sl = smem + OFF_SL_F;
    const unsigned int mb0 = su + OFF_MBAR_B, mb1 = su + OFF_MBAR_B + 8;

    const int warp = tid >> 5, lane = tid & 31;
    const int ri = lane & 15, ci = lane >> 4;
    const int wk = (NSETS == 2) ? (warp & 7) : warp;
    const float* wt = (NSETS == 2 && warp >= 8) ? wt1 : wt0;

    unsigned long long acc[4][4];
#pragma unroll
    for (int i = 0; i < 4; ++i)
#pragma unroll
        for (int j = 0; j < 4; ++j) acc[i][j] = 0ULL;

#pragma unroll
    for (int ph = 0; ph < NPH; ++ph) {
        const float* sa = ph ? srcA1 : srcA0;
        const float* wcolp = wt + (long long)(ci * 512 + colbase) * wstride
                             + ph * 512;
        if (tid == 0) {
            bulk_stage(su, sa, HALF_B, mb0);
            bulk_stage(su + HALF_B, sa + 32 * AST, HALF_B, mb1);
        }
        mbar_wait(mb0, (unsigned int)(par & 1));
        gemm_rows<NSETS, 0>(as, wcolp, wstride, wk, ri, acc);
        mbar_wait(mb1, (unsigned int)(par & 1));
        gemm_rows<NSETS, 2>(as, wcolp, wstride, wk, ri, acc);
        par ^= 1;
        __syncthreads();   // A consumed: safe to restage / overlay
    }

    // --- dump per-warp K-partials into the (dead) A region ---
    float* bufred = as;
#pragma unroll
    for (int i = 0; i < 4; ++i)
#pragma unroll
        for (int j = 0; j < 4; ++j) {
            float2 f = *reinterpret_cast<float2*>(&acc[i][j]);
            bufred[warp * 512 + (ri + 16 * i) * 8 + (4 * ci + j)] = f.x + f.y;
        }
    __syncthreads();

    // --- cross-warp reduce, both sets concurrently ---
    for (int idx = tid; idx < 512 * NSETS; idx += NTHREADS) {
        int set = idx >> 9, o = idx & 511;
        int wbase = (NSETS == 2) ? (set * 8) : 0;
        constexpr int WCNT = (NSETS == 2) ? 8 : 16;
        float v = 0.f;
#pragma unroll
        for (int w = 0; w < WCNT; ++w) v += bufred[(wbase + w) * 512 + o];
        ch[set * 512 + o] = v;
    }
    __syncthreads();

    // --- gated elementwise ---
    for (int idx = tid; idx < 256 * NSETS; idx += NTHREADS) {
        int s = idx >> 8, r = idx & 255;
        int b = r >> 2, pj = r & 3;
        int act = (s == 0) ? act0 : act1;
        int pred = (s == 0) ? pred0 : pred1;
        int st = (s == 0) ? st0 : st1;
        float* gd = (s == 0) ? gd0 : gd1;
        float gv = ch[s * 512 + b * 8 + pj];
        float cv = ch[s * 512 + b * 8 + 4 + pj];
        float gate = 1.f / (1.f + expf(-gv));
        float hh;
        if (act == 0)      hh = tanhf(cv);
        else if (act == 1) hh = fmaxf(cv, 0.f);
        else if (act == 2) hh = 1.f / (1.f + expf(-cv));
        else               hh = cv;
        float sp = (pred < 0) ? hprev[b * AST + colbase + pj]
                              : sl[pred * 256 + b * 4 + pj];
        float sv = fmaf(gate, hh - sp, sp);
        sl[st * 256 + b * 4 + pj] = sv;
        if (gd) gd[b * AST + colbase + pj] = sv;
    }
    __syncthreads();
}

// ---------- prep: transpose W0 (1024x1024) and Ws (8x 512x1024) ----------
__global__ void wt_transpose_kernel(const float* __restrict__ W0,
                                    const float* __restrict__ Ws) {
    __shared__ float tile[32][33];
    int z = blockIdx.z;
    const float* src;
    float* dst;
    int R;
    if (z == 0) { src = W0; dst = g_wt0; R = 1024; }
    else        { src = Ws + (size_t)(z - 1) * 512 * 1024; dst = g_wts[z - 1]; R = 512; }
    int rb = blockIdx.y * 32, cb = blockIdx.x * 32;
    if (rb >= R) return;
#pragma unroll
    for (int i = 0; i < 4; ++i) {
        int r = rb + threadIdx.y + i * 8;
        tile[threadIdx.y + i * 8][threadIdx.x] = src[(size_t)r * 1024 + cb + threadIdx.x];
    }
    __syncthreads();
#pragma unroll
    for (int i = 0; i < 4; ++i) {
        int c = cb + threadIdx.y + i * 8;
        dst[(size_t)c * R + rb + threadIdx.x] = tile[threadIdx.x][threadIdx.y + i * 8];
    }
}

// ---------- prep: pad x into g_xpad, h0 into g_hpad (stride 516) ----------
__global__ void pad_kernel(const float* __restrict__ x,
                           const float* __restrict__ h0) {
    int t = blockIdx.x;
    const float* src = (t < TT) ? (x + (size_t)t * BB * 512) : h0;
    float* dst = (t < TT) ? (g_xpad + (size_t)t * APF) : g_hpad;
    for (int idx = threadIdx.x; idx < BB * 512; idx += blockDim.x) {
        int r = idx >> 9, k = idx & 511;
        dst[r * AST + k] = src[idx];
    }
}

__global__ void __launch_bounds__(NTHREADS, 1)
nao_kernel(float* __restrict__ out, long long out_size) {
    extern __shared__ unsigned char smemRaw[];
    float* smem = reinterpret_cast<float*>(smemRaw);
    float* sl = smem + OFF_SL_F;
    const unsigned int su =
        (unsigned int)__cvta_generic_to_shared(smemRaw);
    const int tid = threadIdx.x;
    const int colbase = blockIdx.x * 4;

    if (tid == 0) {
        asm volatile("mbarrier.init.shared.b64 [%0], 1;"
                     :: "r"(su + OFF_MBAR_B) : "memory");
        asm volatile("mbarrier.init.shared.b64 [%0], 1;"
                     :: "r"(su + OFF_MBAR_B + 8) : "memory");
    }
    __syncthreads();
    int par = 0;

    for (int t = 0; t < TT; ++t) {
        // Level 0: s0 from [x;h] @ W0 (two K=512 accumulate phases)
        do_level<1, 2>(smem, su, tid, g_xpad + (size_t)t * APF, g_hpad,
                       g_wt0, nullptr, 1024, colbase,
                       0, 0, -1, 0, 0, 0, g_spad[0], nullptr, g_hpad, par);
        grid_bar(tid);
        // Level 1: s1 (tanh), s2 (relu), both from s0
        do_level<2, 1>(smem, su, tid, g_spad[0], nullptr, g_wts[0], g_wts[1],
                       512, colbase, 0, 1, 0, 0, 1, 2,
                       g_spad[1], g_spad[2], nullptr, par);
        grid_bar(tid);
        // Level 2: s3 (sigm), s4 (id) from s1; s5 (tanh), s6 (relu) from s2
        do_level<2, 1>(smem, su, tid, g_spad[1], nullptr, g_wts[2], g_wts[3],
                       512, colbase, 2, 3, 1, 1, 3, 4,
                       g_spad[3], g_spad[4], nullptr, par);
        do_level<2, 1>(smem, su, tid, g_spad[2], nullptr, g_wts[4], g_wts[5],
                       512, colbase, 0, 1, 2, 2, 5, 6,
                       nullptr, nullptr, nullptr, par);
        grid_bar(tid);
        // Level 3: s7 (sigm) from s3; s8 (id) from s4
        do_level<1, 1>(smem, su, tid, g_spad[3], nullptr, g_wts[6], nullptr,
                       512, colbase, 2, 0, 3, 0, 7, 0,
                       nullptr, nullptr, nullptr, par);
        do_level<1, 1>(smem, su, tid, g_spad[4], nullptr, g_wts[7], nullptr,
                       512, colbase, 3, 0, 4, 0, 8, 0,
                       nullptr, nullptr, nullptr, par);
        // h_new = mean(s1..s8): write unpadded out + padded g_hpad
        if (tid < 256) {
            const int b = tid >> 2, pj = tid & 3;
            float m = 0.f;
#pragma unroll
            for (int s2 = 1; s2 <= 8; ++s2) m += sl[s2 * 256 + b * 4 + pj];
            m *= 0.125f;
            out[(size_t)t * BB * HH + b * 512 + colbase + pj] = m;
            g_hpad[b * AST + colbase + pj] = m;
            if (t == TT - 1 &&
                out_size >= (long long)TT * BB * HH + (long long)BB * HH)
                out[(size_t)TT * BB * HH + b * 512 + colbase + pj] = m;
        }
        grid_bar(tid);
    }
}

extern "C" void kernel_launch(void* const* d_in, const int* in_sizes, int n_in,
                              void* d_out, int out_size) {
    const float* x  = (const float*)d_in[0];
    const float* h0 = (const float*)d_in[1];
    const float* W0 = (const float*)d_in[2];
    const float* Ws = (const float*)d_in[3];
    float* out = (float*)d_out;

    dim3 tg(32, 32, 9), tb(32, 8);
    wt_transpose_kernel<<<tg, tb>>>(W0, Ws);
    pad_kernel<<<TT + 1, 256>>>(x, h0);

    cudaFuncSetAttribute(nao_kernel, cudaFuncAttributeMaxDynamicSharedMemorySize,
                         SMEM_TOTAL);
    nao_kernel<<<GRID, NTHREADS, SMEM_TOTAL>>>(out, (long long)out_size);
}

// round 9
// speedup vs baseline: 1.7674x; 1.7674x over previous
#include <cuda_runtime.h>
#include <math.h>
#include <stdint.h>

#define TT 512
#define BB 64
#define HH 512
#define GRID 128
#define NTHREADS 512
#define CK 16              // k's per chunk
#define WST 20             // A buffer row stride in floats (conflict-free phases)
#define WBUF_F (64 * WST)  // 1280 floats per A chunk buffer

// ---- smem layout (float offsets) ----
#define OFF_A    0
#define SZ_A_F   (16 * 2 * WBUF_F)        // 40960 fl (163,840 B)
#define OFF_W_F  SZ_A_F                   // 16 warps * 2 bufs * 128 fl
#define SZ_W_F   (16 * 2 * 128)           // 4096 fl
#define OFF_CH_F (OFF_W_F + SZ_W_F)       // 45056
#define OFF_SL_F (OFF_CH_F + 1024)        // 46080
#define SMEM_FLOATS (OFF_SL_F + 2304)     // 48384
#define SMEM_TOTAL (SMEM_FLOATS * 4)      // 193,536 B -> 1 CTA/SM

// ---------------- device globals (no allocation allowed) ----------------
__device__ unsigned long long g_arrive;
__device__ unsigned long long g_release;
__device__ float g_s[5][BB * HH];         // states s0..s4, [64 x 512] row-major
__device__ float g_wt0[1024 * 1024];      // W0^T  [col][k]    (4 MB)
__device__ float g_wts[8][1024 * 512];    // Ws^T  [i][col][k] (16 MB)

__device__ __forceinline__ void fma2(unsigned long long &d, unsigned long long a,
                                     unsigned long long b) {
    asm("fma.rn.f32x2 %0, %1, %2, %0;" : "+l"(d) : "l"(a), "l"(b));
}

// Monotonic grid barrier: safe across graph replays (counters never reset).
// 128 CTAs co-resident (1 CTA/SM via 193KB smem), so spinning is safe.
__device__ __forceinline__ void grid_bar(int tid) {
    __syncthreads();
    if (tid == 0) {
        __threadfence();
        unsigned long long a = atomicAdd(&g_arrive, 1ULL) + 1ULL;
        unsigned long long phase = (a + (GRID - 1)) / GRID;
        if (a == phase * (unsigned long long)GRID) {
            asm volatile("st.release.gpu.u64 [%0], %1;"
                         :: "l"(&g_release), "l"(phase) : "memory");
        } else {
            unsigned long long v;
            do {
                asm volatile("ld.acquire.gpu.u64 %0, [%1];"
                             : "=l"(v) : "l"(&g_release) : "memory");
            } while (v < phase);
        }
        __threadfence();
    }
    __syncthreads();
}

__device__ __forceinline__ void cpasync16(float* dst, const float* src) {
    unsigned int da = (unsigned int)__cvta_generic_to_shared(dst);
    asm volatile("cp.async.cg.shared.global [%0], [%1], 16;" :: "r"(da), "l"(src));
}

// Warp-private stage of one chunk: A = [64 rows x 16 k] slice + W = [8 cols x 16 k].
// 9 cp.async per lane; one commit group. No cross-warp coordination.
__device__ __forceinline__ void stage_chunk(int lane, float* abuf, float* wbuf,
        const float* __restrict__ s0, const float* __restrict__ s1, int k0,
        const float* __restrict__ wt, long long wstride, int colbase) {
    const float* src = (k0 < 512) ? (s0 + k0) : (s1 + (k0 - 512));
#pragma unroll
    for (int l = 0; l < 8; ++l) {
        int f = lane + 32 * l;            // 0..255 float4s
        int row = f >> 2, kq = (f & 3) * 4;
        cpasync16(abuf + row * WST + kq, src + row * 512 + kq);
    }
    {
        int c8 = lane >> 2, kq = (lane & 3) * 4;
        int gcol = (c8 < 4) ? (colbase + c8) : (512 + colbase + c8 - 4);
        cpasync16(wbuf + c8 * CK + kq, wt + (long long)gcol * wstride + k0 + kq);
    }
    asm volatile("cp.async.commit_group;");
}

// Compute one 16-k chunk from warp-private smem buffers.
__device__ __forceinline__ void compute_chunk(const float* __restrict__ abuf,
        const float* __restrict__ wbuf, int ri, int ci,
        unsigned long long (&acc)[4][4]) {
#pragma unroll
    for (int t4 = 0; t4 < 4; ++t4) {
        ulonglong2 a2[4], w2[4];
#pragma unroll
        for (int i = 0; i < 4; ++i)
            a2[i] = *reinterpret_cast<const ulonglong2*>(
                abuf + (ri + 16 * i) * WST + t4 * 4);
#pragma unroll
        for (int j = 0; j < 4; ++j)
            w2[j] = *reinterpret_cast<const ulonglong2*>(
                wbuf + (4 * ci + j) * CK + t4 * 4);
#pragma unroll
        for (int j = 0; j < 4; ++j)
#pragma unroll
            for (int i = 0; i < 4; ++i) {
                fma2(acc[i][j], a2[i].x, w2[j].x);
                fma2(acc[i][j], a2[i].y, w2[j].y);
            }
    }
}

// One DAG level. KTOT = total K (1024 for L0, else 512).
// NSETS==2: warps 0-7 set0, warps 8-15 set1. Zero CTA syncs in the K loop.
template <int NSETS, int KTOT>
__device__ __forceinline__ void do_level(float* smem, int tid,
        const float* __restrict__ srcA0, const float* __restrict__ srcA1,
        const float* wt0, const float* wt1, long long wstride, int colbase,
        int act0, int act1, int pred0, int pred1, int st0, int st1,
        float* gd0, float* gd1, const float* __restrict__ hprev) {
    float* ch = smem + OFF_CH_F;
    float* sl = smem + OFF_SL_F;

    const int warp = tid >> 5, lane = tid & 31;
    const int ri = lane & 15, ci = lane >> 4;
    const int wk = (NSETS == 2) ? (warp & 7) : warp;
    constexpr int KW = KTOT / ((NSETS == 2) ? 8 : 16);
    constexpr int NCH = KW / CK;
    const float* wt = (NSETS == 2 && warp >= 8) ? wt1 : wt0;

    float* abase = smem + warp * (2 * WBUF_F);
    float* wbase = smem + OFF_W_F + warp * (2 * 128);
    const int kb = wk * KW;

    unsigned long long acc[4][4];
#pragma unroll
    for (int i = 0; i < 4; ++i)
#pragma unroll
        for (int j = 0; j < 4; ++j) acc[i][j] = 0ULL;

    stage_chunk(lane, abase, wbase, srcA0, srcA1, kb, wt, wstride, colbase);
    stage_chunk(lane, abase + WBUF_F, wbase + 128, srcA0, srcA1, kb + CK,
                wt, wstride, colbase);
#pragma unroll
    for (int c = 0; c < NCH; ++c) {
        if (c < NCH - 1)
            asm volatile("cp.async.wait_group 1;" ::: "memory");
        else
            asm volatile("cp.async.wait_group 0;" ::: "memory");
        compute_chunk(abase + (c & 1) * WBUF_F, wbase + (c & 1) * 128,
                      ri, ci, acc);
        if (c + 2 < NCH)
            stage_chunk(lane, abase + (c & 1) * WBUF_F, wbase + (c & 1) * 128,
                        srcA0, srcA1, kb + (c + 2) * CK, wt, wstride, colbase);
    }
    __syncthreads();   // all warps done with A region before partial-dump overlay

    // --- dump per-warp K-partials into the (dead) A region ---
    float* red = smem;
#pragma unroll
    for (int i = 0; i < 4; ++i) {
        float4 v;
        float2 f0 = *reinterpret_cast<float2*>(&acc[i][0]);
        float2 f1 = *reinterpret_cast<float2*>(&acc[i][1]);
        float2 f2 = *reinterpret_cast<float2*>(&acc[i][2]);
        float2 f3 = *reinterpret_cast<float2*>(&acc[i][3]);
        v.x = f0.x + f0.y; v.y = f1.x + f1.y;
        v.z = f2.x + f2.y; v.w = f3.x + f3.y;
        *reinterpret_cast<float4*>(
            red + warp * 512 + (ri + 16 * i) * 8 + 4 * ci) = v;
    }
    __syncthreads();

    // --- cross-warp reduce, both sets concurrently ---
    for (int idx = tid; idx < 512 * NSETS; idx += NTHREADS) {
        int set = idx >> 9, o = idx & 511;
        int wbaseW = (NSETS == 2) ? (set * 8) : 0;
        constexpr int WCNT = (NSETS == 2) ? 8 : 16;
        float v = 0.f;
#pragma unroll
        for (int w = 0; w < WCNT; ++w) v += red[(wbaseW + w) * 512 + o];
        ch[set * 512 + o] = v;
    }
    __syncthreads();

    // --- gated elementwise ---
    for (int idx = tid; idx < 256 * NSETS; idx += NTHREADS) {
        int s = idx >> 8, r = idx & 255;
        int b = r >> 2, pj = r & 3;
        int act = (s == 0) ? act0 : act1;
        int pred = (s == 0) ? pred0 : pred1;
        int st = (s == 0) ? st0 : st1;
        float* gd = (s == 0) ? gd0 : gd1;
        float gv = ch[s * 512 + b * 8 + pj];
        float cv = ch[s * 512 + b * 8 + 4 + pj];
        float gate = 1.f / (1.f + expf(-gv));
        float hh;
        if (act == 0)      hh = tanhf(cv);
        else if (act == 1) hh = fmaxf(cv, 0.f);
        else if (act == 2) hh = 1.f / (1.f + expf(-cv));
        else               hh = cv;
        float sp = (pred < 0) ? hprev[b * 512 + colbase + pj]
                              : sl[pred * 256 + b * 4 + pj];
        float sv = fmaf(gate, hh - sp, sp);
        sl[st * 256 + b * 4 + pj] = sv;
        if (gd) gd[b * 512 + colbase + pj] = sv;
    }
    __syncthreads();
}

// ---------- prep: transpose W0 (1024x1024) and Ws (8x 512x1024) ----------
__global__ void wt_transpose_kernel(const float* __restrict__ W0,
                                    const float* __restrict__ Ws) {
    __shared__ float tile[32][33];
    int z = blockIdx.z;
    const float* src;
    float* dst;
    int R;
    if (z == 0) { src = W0; dst = g_wt0; R = 1024; }
    else        { src = Ws + (size_t)(z - 1) * 512 * 1024; dst = g_wts[z - 1]; R = 512; }
    int rb = blockIdx.y * 32, cb = blockIdx.x * 32;
    if (rb >= R) return;
#pragma unroll
    for (int i = 0; i < 4; ++i) {
        int r = rb + threadIdx.y + i * 8;
        tile[threadIdx.y + i * 8][threadIdx.x] = src[(size_t)r * 1024 + cb + threadIdx.x];
    }
    __syncthreads();
#pragma unroll
    for (int i = 0; i < 4; ++i) {
        int c = cb + threadIdx.y + i * 8;
        dst[(size_t)c * R + rb + threadIdx.x] = tile[threadIdx.x][threadIdx.y + i * 8];
    }
}

__global__ void __launch_bounds__(NTHREADS, 1)
nao_kernel(const float* __restrict__ x, const float* __restrict__ h0,
           float* __restrict__ out, long long out_size) {
    extern __shared__ unsigned char smemRaw[];
    float* smem = reinterpret_cast<float*>(smemRaw);
    float* sl = smem + OFF_SL_F;
    const int tid = threadIdx.x;
    const int colbase = blockIdx.x * 4;

    for (int t = 0; t < TT; ++t) {
        const float* xt = x + (size_t)t * BB * 512;
        const float* hRow = (t == 0) ? h0 : (out + (size_t)(t - 1) * BB * HH);

        // Level 0: s0 from [x;h] @ W0 (warps 0-7 cover x-k, 8-15 cover h-k)
        do_level<1, 1024>(smem, tid, xt, hRow, g_wt0, nullptr, 1024, colbase,
                          0, 0, -1, 0, 0, 0, g_s[0], nullptr, hRow);
        grid_bar(tid);
        // Level 1: s1 (tanh), s2 (relu), both from s0
        do_level<2, 512>(smem, tid, g_s[0], nullptr, g_wts[0], g_wts[1], 512,
                         colbase, 0, 1, 0, 0, 1, 2, g_s[1], g_s[2], nullptr);
        grid_bar(tid);
        // Level 2: s3 (sigm), s4 (id) from s1; s5 (tanh), s6 (relu) from s2
        do_level<2, 512>(smem, tid, g_s[1], nullptr, g_wts[2], g_wts[3], 512,
                         colbase, 2, 3, 1, 1, 3, 4, g_s[3], g_s[4], nullptr);
        do_level<2, 512>(smem, tid, g_s[2], nullptr, g_wts[4], g_wts[5], 512,
                         colbase, 0, 1, 2, 2, 5, 6, nullptr, nullptr, nullptr);
        grid_bar(tid);
        // Level 3: s7 (sigm) from s3; s8 (id) from s4
        do_level<1, 512>(smem, tid, g_s[3], nullptr, g_wts[6], nullptr, 512,
                         colbase, 2, 0, 3, 0, 7, 0, nullptr, nullptr, nullptr);
        do_level<1, 512>(smem, tid, g_s[4], nullptr, g_wts[7], nullptr, 512,
                         colbase, 3, 0, 4, 0, 8, 0, nullptr, nullptr, nullptr);
        // h_new = mean(s1..s8)
        if (tid < 256) {
            const int b = tid >> 2, pj = tid & 3;
            float m = 0.f;
#pragma unroll
            for (int s2 = 1; s2 <= 8; ++s2) m += sl[s2 * 256 + b * 4 + pj];
            m *= 0.125f;
            out[(size_t)t * BB * HH + b * 512 + colbase + pj] = m;
            if (t == TT - 1 &&
                out_size >= (long long)TT * BB * HH + (long long)BB * HH)
                out[(size_t)TT * BB * HH + b * 512 + colbase + pj] = m;
        }
        grid_bar(tid);
    }
}

extern "C" void kernel_launch(void* const* d_in, const int* in_sizes, int n_in,
                              void* d_out, int out_size) {
    const float* x  = (const float*)d_in[0];
    const float* h0 = (const float*)d_in[1];
    const float* W0 = (const float*)d_in[2];
    const float* Ws = (const float*)d_in[3];
    float* out = (float*)d_out;

    dim3 tg(32, 32, 9), tb(32, 8);
    wt_transpose_kernel<<<tg, tb>>>(W0, Ws);

    cudaFuncSetAttribute(nao_kernel, cudaFuncAttributeMaxDynamicSharedMemorySize,
                         SMEM_TOTAL);
    nao_kernel<<<GRID, NTHREADS, SMEM_TOTAL>>>(x, h0, out, (long long)out_size);
}